// round 14
// baseline (speedup 1.0000x reference)
#include <cuda_runtime.h>
#include <cuda_fp16.h>
#include <cstdio>
#include <cstdint>

#define BB 4
#define LL 1024
#define DIN 8
#define DMODEL 512
#define NDEPTH 4
#define DINNER 1024
#define DSTATE 16
#define DCONV 4
#define DTRANK 32
#define MROWS (BB*LL)   /* 4096 */

#define CLEN 64
#define NCHK 16
#define CHST4 (BB*DINNER*DSTATE/4)   /* 16384 float4 per chunk */

// ---------------- scratch ----------------
__device__ float  g_h[MROWS*DMODEL];
__device__ float  g_xz[MROWS*DINNER];     // xc half only now (ldc = DINNER)
__device__ float  g_xdbl[MROWS*64];
__device__ float  g_dt[MROWS*DINNER];
__device__ float  g_part[4*MROWS*64];
__device__ float4 g_hend4[NCHK*CHST4];
__device__ float4 g_aprod4[NCHK*CHST4];
__device__ float4 g_h04[NCHK*CHST4];

__device__ __half g_h16[MROWS*DMODEL];
__device__ __half g_u16[MROWS*DINNER];
__device__ __half g_sz16[MROWS*DINNER];
__device__ __half g_y16[MROWS*DINNER];
__device__ __half g_dtlr16[MROWS*DTRANK];
__device__ __half g_w16[6684672];

#define OFF_XZ  0
#define SZ_XZ_L (2048*512)
#define OFF_XP  4194304
#define SZ_XP_L (64*1024)
#define OFF_DT  4456448
#define SZ_DT_L (1024*32)
#define OFF_OUT 4587520
#define SZ_OUT_L (512*1024)

#define LOG2E 1.4426950408889634f

// ---------------- helpers ----------------
__device__ __forceinline__ float fx2(float x){ float y; asm("ex2.approx.f32 %0,%1;" : "=f"(y) : "f"(x)); return y; }
__device__ __forceinline__ float fexp(float x){ return fx2(x*LOG2E); }
__device__ __forceinline__ float fsilu(float x){ return x/(1.f+fexp(-x)); }
__device__ __forceinline__ uint32_t smem_u32(const void* p){
    uint32_t a; asm("{ .reg .u64 t; cvta.to.shared.u64 t, %1; cvt.u32.u64 %0, t; }" : "=r"(a) : "l"(p));
    return a;
}

#define LDSM4(r0,r1,r2,r3,addr) \
    asm volatile("ldmatrix.sync.aligned.m8n8.x4.shared.b16 {%0,%1,%2,%3}, [%4];" \
        : "=r"(r0),"=r"(r1),"=r"(r2),"=r"(r3) : "r"(addr))

#define MMA16816(d, a, b) \
    asm volatile("mma.sync.aligned.m16n8k16.row.col.f32.f16.f16.f32 " \
        "{%0,%1,%2,%3}, {%4,%5,%6,%7}, {%8,%9}, {%0,%1,%2,%3};" \
        : "+f"((d)[0]), "+f"((d)[1]), "+f"((d)[2]), "+f"((d)[3]) \
        : "r"((a)[0]), "r"((a)[1]), "r"((a)[2]), "r"((a)[3]), \
          "r"((b)[0]), "r"((b)[1]))

#define CP_ASYNC16(saddr, gptr) \
    asm volatile("cp.async.cg.shared.global [%0], [%1], 16;" :: "r"(saddr), "l"(gptr))
#define CP_COMMIT() asm volatile("cp.async.commit_group;")
#define CP_WAIT(n)  asm volatile("cp.async.wait_group %0;" :: "n"(n))

// ---------------- fp32 -> fp16 conversion ----------------
__global__ void f2h_kernel(const float* __restrict__ s, __half* __restrict__ d, int n4){
    int i = blockIdx.x*blockDim.x + threadIdx.x;
    if (i >= n4) return;
    float4 v = reinterpret_cast<const float4*>(s)[i];
    __half2* o = reinterpret_cast<__half2*>(d);
    o[2*i]   = __floats2half2_rn(v.x, v.y);
    o[2*i+1] = __floats2half2_rn(v.z, v.w);
}

// ---------------- input projection ----------------
__global__ void inproj_kernel(const float* __restrict__ x, const float* __restrict__ w,
                              const float* __restrict__ b){
    int idx = blockIdx.x*blockDim.x + threadIdx.x;
    if (idx >= MROWS*DMODEL) return;
    int m = idx / DMODEL, d = idx % DMODEL;
    const float* xr = x + m*DIN;
    const float* wr = w + d*DIN;
    float acc = b[d];
#pragma unroll
    for (int i = 0; i < DIN; i++) acc += xr[i]*wr[i];
    g_h16[idx] = __float2half(acc);
}

// ---------------- fp16 NT GEMM, 64x64 warp tiles (xz / out) ----------------
// EPI: 0 fp32 only | 2 fp32 + fp16 | 3 fp16 only |
//      4 xz-split: col0 <  DINNER -> fp32 xc to C (ldc)
//                  col0 >= DINNER -> silu -> fp16 to C16 (ldc16), col - DINNER
template<int EPI>
__global__ __launch_bounds__(128, 2)
void gemm_w64(const __half* __restrict__ A, const __half* __restrict__ B, float* __restrict__ C,
              int K, int lda, int ldb, int ldc, __half* __restrict__ C16, int ldc16)
{
    constexpr int BK = 32, STG = 4, ROWB = 80;
    constexpr int ABYTES = 128*ROWB;
    constexpr int STGB = 2*ABYTES;

    extern __shared__ char smem[];
    const uint32_t sb = smem_u32(smem);
    const int tid = threadIdx.x, wid = tid >> 5, lane = tid & 31;
    const int wm = wid & 1, wn = wid >> 1;
    const int row0 = blockIdx.y*128, col0 = blockIdx.x*128;
    const int ntiles = K / BK;

    const __half* Ag = A + (size_t)row0*lda;
    const __half* Bg = B + (size_t)col0*ldb;

    float acc[4][8][4];
#pragma unroll
    for (int i = 0; i < 4; i++)
#pragma unroll
        for (int j = 0; j < 8; j++)
#pragma unroll
            for (int q = 0; q < 4; q++) acc[i][j][q] = 0.f;

    auto issue = [&](int t){
        int buf = t & (STG-1);
        uint32_t as = sb + buf*STGB;
        uint32_t bs = as + ABYTES;
        int kt = t*BK;
#pragma unroll
        for (int it = 0; it < 4; it++){
            int i = it*128 + tid;
            int r = i >> 2, c = i & 3;
            CP_ASYNC16(as + r*ROWB + c*16, Ag + (size_t)r*lda + kt + c*8);
        }
#pragma unroll
        for (int it = 0; it < 4; it++){
            int i = it*128 + tid;
            int r = i >> 2, c = i & 3;
            CP_ASYNC16(bs + r*ROWB + c*16, Bg + (size_t)r*ldb + kt + c*8);
        }
        CP_COMMIT();
    };

    auto compute = [&](int t){
        int buf = t & (STG-1);
        uint32_t as = sb + buf*STGB + wm*64*ROWB;
        uint32_t bs = sb + buf*STGB + ABYTES + wn*64*ROWB;
#pragma unroll
        for (int s = 0; s < 2; s++){
            uint32_t a[4][4];
#pragma unroll
            for (int im = 0; im < 4; im++){
                uint32_t addr = as + (im*16 + (lane & 7) + ((lane >> 3) & 1)*8)*ROWB
                              + (2*s + (lane >> 4))*16;
                LDSM4(a[im][0], a[im][1], a[im][2], a[im][3], addr);
            }
            uint32_t b[8][2];
#pragma unroll
            for (int j = 0; j < 4; j++){
                uint32_t addr = bs + (j*16 + (lane & 7) + (lane >> 4)*8)*ROWB
                              + (2*s + ((lane >> 3) & 1))*16;
                LDSM4(b[2*j][0], b[2*j][1], b[2*j+1][0], b[2*j+1][1], addr);
            }
#pragma unroll
            for (int im = 0; im < 4; im++)
#pragma unroll
                for (int j = 0; j < 8; j++)
                    MMA16816(acc[im][j], a[im], b[j]);
        }
    };

#pragma unroll
    for (int i = 0; i < STG-1; i++)
        if (i < ntiles) issue(i);

    for (int t = 0; t < ntiles; t++){
        int rem = ntiles - 1 - t;
        if (rem >= 2)      { CP_WAIT(2); }
        else if (rem == 1) { CP_WAIT(1); }
        else               { CP_WAIT(0); }
        __syncthreads();
        if (t + STG-1 < ntiles) issue(t + STG-1);
        compute(t);
    }

    const bool zhalf = (EPI == 4) && (col0 >= DINNER);
#pragma unroll
    for (int im = 0; im < 4; im++){
        int r = row0 + wm*64 + im*16 + (lane >> 2);
#pragma unroll
        for (int j = 0; j < 8; j++){
            int c = col0 + wn*64 + j*8 + (lane & 3)*2;
            float v0 = acc[im][j][0], v1 = acc[im][j][1];
            float v2 = acc[im][j][2], v3 = acc[im][j][3];
            if (EPI == 4){
                if (!zhalf){
                    *reinterpret_cast<float2*>(&C[(size_t)r*ldc + c])     = make_float2(v0, v1);
                    *reinterpret_cast<float2*>(&C[(size_t)(r+8)*ldc + c]) = make_float2(v2, v3);
                } else {
                    int cz = c - DINNER;
                    *reinterpret_cast<__half2*>(&C16[(size_t)r*ldc16 + cz]) =
                        __floats2half2_rn(fsilu(v0), fsilu(v1));
                    *reinterpret_cast<__half2*>(&C16[(size_t)(r+8)*ldc16 + cz]) =
                        __floats2half2_rn(fsilu(v2), fsilu(v3));
                }
            } else {
                if (EPI != 3){
                    *reinterpret_cast<float2*>(&C[(size_t)r*ldc + c])     = make_float2(v0, v1);
                    *reinterpret_cast<float2*>(&C[(size_t)(r+8)*ldc + c]) = make_float2(v2, v3);
                }
                if (EPI == 2 || EPI == 3){
                    *reinterpret_cast<__half2*>(&C16[(size_t)r*ldc16 + c])     = __floats2half2_rn(v0, v1);
                    *reinterpret_cast<__half2*>(&C16[(size_t)(r+8)*ldc16 + c]) = __floats2half2_rn(v2, v3);
                }
            }
        }
    }
}

// ---------------- fp16 NT GEMM, 256 threads (xp split-K / dt) ----------------
template<int BN, int EPI>
__global__ __launch_bounds__(256, 2)
void gemm_h(const __half* __restrict__ A, const __half* __restrict__ B, float* __restrict__ C,
            int K, int lda, int ldb, int ldc, const float* __restrict__ bias,
            int partStride)
{
    constexpr int BM = 128, BK = 32, STG = 4;
    constexpr int NW  = BN/2;
    constexpr int NFR = NW/8;
    constexpr int ROWB = 80;
    constexpr int ABYTES = BM*ROWB;
    constexpr int BBYTES = BN*ROWB;
    constexpr int STGB = ABYTES + BBYTES;

    extern __shared__ char smem[];
    const uint32_t sb = smem_u32(smem);
    const int tid = threadIdx.x, wid = tid >> 5, lane = tid & 31;
    const int wm = wid & 3, wn = wid >> 2;
    const int row0 = blockIdx.y*BM, col0 = blockIdx.x*BN;
    const int kslice = K / gridDim.z;
    const int k0 = blockIdx.z * kslice;
    const int ntiles = kslice / BK;

    const __half* Ag = A + (size_t)row0*lda + k0;
    const __half* Bg = B + (size_t)col0*ldb + k0;
    float* Cp = C + (size_t)blockIdx.z * partStride;

    float acc[2][NFR][4];
#pragma unroll
    for (int i = 0; i < 2; i++)
#pragma unroll
        for (int j = 0; j < NFR; j++)
#pragma unroll
            for (int q = 0; q < 4; q++) acc[i][j][q] = 0.f;

    auto issue = [&](int t){
        int buf = t & (STG-1);
        uint32_t as = sb + buf*STGB;
        uint32_t bs = as + ABYTES;
        int kt = t*BK;
#pragma unroll
        for (int it = 0; it < 2; it++){
            int i = it*256 + tid;
            int r = i >> 2, c = i & 3;
            CP_ASYNC16(as + r*ROWB + c*16, Ag + (size_t)r*lda + kt + c*8);
        }
#pragma unroll
        for (int it = 0; it < BN/64; it++){
            int i = it*256 + tid;
            int r = i >> 2, c = i & 3;
            CP_ASYNC16(bs + r*ROWB + c*16, Bg + (size_t)r*ldb + kt + c*8);
        }
        CP_COMMIT();
    };

    auto compute = [&](int t){
        int buf = t & (STG-1);
        uint32_t as = sb + buf*STGB + wm*32*ROWB;
        uint32_t bs = sb + buf*STGB + ABYTES + wn*NW*ROWB;
#pragma unroll
        for (int s = 0; s < 2; s++){
            uint32_t a[2][4];
#pragma unroll
            for (int im = 0; im < 2; im++){
                uint32_t addr = as + (im*16 + (lane & 7) + ((lane >> 3) & 1)*8)*ROWB
                              + (2*s + (lane >> 4))*16;
                LDSM4(a[im][0], a[im][1], a[im][2], a[im][3], addr);
            }
            uint32_t b[NFR][2];
#pragma unroll
            for (int j = 0; j < NFR/2; j++){
                uint32_t addr = bs + (j*16 + (lane & 7) + (lane >> 4)*8)*ROWB
                              + (2*s + ((lane >> 3) & 1))*16;
                LDSM4(b[2*j][0], b[2*j][1], b[2*j+1][0], b[2*j+1][1], addr);
            }
#pragma unroll
            for (int im = 0; im < 2; im++)
#pragma unroll
                for (int j = 0; j < NFR; j++)
                    MMA16816(acc[im][j], a[im], b[j]);
        }
    };

#pragma unroll
    for (int i = 0; i < STG-1; i++)
        if (i < ntiles) issue(i);

    for (int t = 0; t < ntiles; t++){
        int rem = ntiles - 1 - t;
        if (rem >= 2)      { CP_WAIT(2); }
        else if (rem == 1) { CP_WAIT(1); }
        else               { CP_WAIT(0); }
        __syncthreads();
        if (t + STG-1 < ntiles) issue(t + STG-1);
        compute(t);
    }

#pragma unroll
    for (int im = 0; im < 2; im++){
        int r = row0 + wm*32 + im*16 + (lane >> 2);
#pragma unroll
        for (int j = 0; j < NFR; j++){
            int c = col0 + wn*NW + j*8 + (lane & 3)*2;
            float v0 = acc[im][j][0], v1 = acc[im][j][1];
            float v2 = acc[im][j][2], v3 = acc[im][j][3];
            if (EPI == 1){
                float b0 = bias[c], b1 = bias[c+1];
                v0 += b0; v1 += b1; v2 += b0; v3 += b1;
                v0 = (v0 > 20.f) ? v0 : log1pf(fexp(v0));
                v1 = (v1 > 20.f) ? v1 : log1pf(fexp(v1));
                v2 = (v2 > 20.f) ? v2 : log1pf(fexp(v2));
                v3 = (v3 > 20.f) ? v3 : log1pf(fexp(v3));
            }
            *reinterpret_cast<float2*>(&Cp[(size_t)r*ldc + c])     = make_float2(v0, v1);
            *reinterpret_cast<float2*>(&Cp[(size_t)(r+8)*ldc + c]) = make_float2(v2, v3);
        }
    }
}

// ---------------- split-K reduce for xp gemm ----------------
__global__ void reduce_xp_kernel(){
    int idx = blockIdx.x*blockDim.x + threadIdx.x;
    if (idx >= MROWS*64) return;
    float s = g_part[idx] + g_part[MROWS*64 + idx]
            + g_part[2*MROWS*64 + idx] + g_part[3*MROWS*64 + idx];
    g_xdbl[idx] = s;
    int col = idx & 63;
    if (col < DTRANK){
        int row = idx >> 6;
        g_dtlr16[row*DTRANK + col] = __float2half(s);
    }
}

// ---------------- causal conv1d + silu (xc only, 4 ch x 4 t / thread) ----------------
__global__ __launch_bounds__(256)
void conv_silu_kernel(const float* __restrict__ cw, const float* __restrict__ cb){
    int idx = blockIdx.x*blockDim.x + threadIdx.x;
    if (idx >= (MROWS/4)*(DINNER/4)) return;
    int rg = idx >> 8;
    int e  = (idx & 255) << 2;
    int b  = rg >> 8;
    int l0 = (rg & 255) << 2;

    float cwa[4][4];
#pragma unroll
    for (int j = 0; j < 4; j++)
        *reinterpret_cast<float4*>(cwa[j]) =
            *reinterpret_cast<const float4*>(cw + (size_t)(e+j)*DCONV);
    float4 bias = *reinterpret_cast<const float4*>(cb + e);

    float4 xv[7];
#pragma unroll
    for (int k = 0; k < 7; k++){
        int lp = l0 - 3 + k;
        if (lp >= 0)
            xv[k] = *reinterpret_cast<const float4*>(
                g_xz + (size_t)(b*LL + lp)*DINNER + e);
        else
            xv[k] = make_float4(0.f, 0.f, 0.f, 0.f);
    }

#pragma unroll
    for (int t = 0; t < 4; t++){
        float4 acc = bias;
#pragma unroll
        for (int k = 0; k < 4; k++){
            float4 xc = xv[t + k];
            acc.x += cwa[0][k]*xc.x;
            acc.y += cwa[1][k]*xc.y;
            acc.z += cwa[2][k]*xc.z;
            acc.w += cwa[3][k]*xc.w;
        }
        int r = b*LL + l0 + t;
        size_t o = (size_t)r*DINNER + e;
        __half2 u01 = __floats2half2_rn(fsilu(acc.x), fsilu(acc.y));
        __half2 u23 = __floats2half2_rn(fsilu(acc.z), fsilu(acc.w));
        uint2 pk;
        pk.x = *reinterpret_cast<uint32_t*>(&u01);
        pk.y = *reinterpret_cast<uint32_t*>(&u23);
        *reinterpret_cast<uint2*>(g_u16 + o) = pk;
    }
}

// ---------------- chunked scan pass A ----------------
template<bool FAST>
__device__ __forceinline__ void scanA_loop(
    const float (*s_dt)[32], const float (*s_bc)[32], const __half (*s_u)[32],
    const __half (*s_sz)[32],
    int col, int sq, const float* a2, float* st, float& sdt, float dp, size_t rowbase)
{
#pragma unroll 4
    for (int tt = 0; tt < CLEN; tt++){
        float dt = s_dt[tt][col];
        float uu = __half2float(s_u[tt][col]);
        float du = dt*uu;
        float4 Bv = *reinterpret_cast<const float4*>(&s_bc[tt][sq*4]);
        float4 Cv = *reinterpret_cast<const float4*>(&s_bc[tt][16 + sq*4]);
        float dA0, dA1, dA2, dA3;
        if (FAST){
            float r = fx2(-dt*LOG2E);
            dA0 = fx2(dt*a2[0]);
            dA1 = dA0*r; dA2 = dA1*r; dA3 = dA2*r;
        } else {
            dA0 = fx2(dt*a2[0]); dA1 = fx2(dt*a2[1]);
            dA2 = fx2(dt*a2[2]); dA3 = fx2(dt*a2[3]);
        }
        st[0] = dA0*st[0] + Bv.x*du;
        st[1] = dA1*st[1] + Bv.y*du;
        st[2] = dA2*st[2] + Bv.z*du;
        st[3] = dA3*st[3] + Bv.w*du;
        sdt += dt;
        float y = st[0]*Cv.x + st[1]*Cv.y + st[2]*Cv.z + st[3]*Cv.w;
        y += __shfl_xor_sync(0xffffffffu, y, 8);
        y += __shfl_xor_sync(0xffffffffu, y, 16);
        if (sq == 0){
            float yo = (y + uu*dp) * __half2float(s_sz[tt][col]);
            g_y16[rowbase + (size_t)tt*DINNER] = __float2half(yo);
        }
    }
}

__global__ __launch_bounds__(128)
void scanA_kernel(const float* __restrict__ A_log, const float* __restrict__ Dp){
    const int b = blockIdx.y, ch = blockIdx.z;
    const int d0 = blockIdx.x*32;
    const int tid = threadIdx.x;
    const int lane = tid & 31;
    const int col = (tid >> 5)*8 + (lane & 7);
    const int d = d0 + col;
    const int sq = lane >> 3;
    const int t0 = ch*CLEN;

    __shared__ __align__(16) float  s_dt[CLEN][32];
    __shared__ __align__(16) float  s_bc[CLEN][32];
    __shared__ __align__(16) __half s_u [CLEN][32];
    __shared__ __align__(16) __half s_sz[CLEN][32];

    for (int i = tid; i < CLEN*8; i += 128){
        int tt = i >> 3, p = (i & 7) << 2;
        size_t g = ((size_t)(b*LL + t0 + tt))*DINNER + d0 + p;
        CP_ASYNC16(smem_u32(&s_dt[tt][p]), g_dt + g);
        size_t gb = ((size_t)(b*LL + t0 + tt))*64 + DTRANK + p;
        CP_ASYNC16(smem_u32(&s_bc[tt][p]), g_xdbl + gb);
    }
    for (int i = tid; i < CLEN*4; i += 128){
        int tt = i >> 2, p = (i & 3) << 3;
        size_t g = ((size_t)(b*LL + t0 + tt))*DINNER + d0 + p;
        CP_ASYNC16(smem_u32(&s_u [tt][p]), g_u16  + g);
        CP_ASYNC16(smem_u32(&s_sz[tt][p]), g_sz16 + g);
    }
    CP_COMMIT(); CP_WAIT(0);
    __syncthreads();

    float a2[4];
    bool fast = true;
#pragma unroll
    for (int k = 0; k < 4; k++){
        float av = expf(A_log[d*DSTATE + sq*4 + k]);
        a2[k] = -av * LOG2E;
        if (fabsf(av - (float)(sq*4 + k + 1)) > 1e-3f) fast = false;
    }
    const float dp = Dp[d];

    float st[4] = {0.f, 0.f, 0.f, 0.f};
    float sdt = 0.f;
    size_t rowbase = ((size_t)(b*LL + t0))*DINNER + d;
    if (fast) scanA_loop<true >(s_dt, s_bc, s_u, s_sz, col, sq, a2, st, sdt, dp, rowbase);
    else      scanA_loop<false>(s_dt, s_bc, s_u, s_sz, col, sq, a2, st, sdt, dp, rowbase);

    float4 he = make_float4(st[0], st[1], st[2], st[3]);
    float4 ap;
    ap.x = fx2(sdt*a2[0]); ap.y = fx2(sdt*a2[1]);
    ap.z = fx2(sdt*a2[2]); ap.w = fx2(sdt*a2[3]);
    int ci = ch*CHST4 + (b*DINNER + d)*4 + sq;
    g_hend4[ci]  = he;
    g_aprod4[ci] = ap;
}

// ---------------- chunked scan: middle combine ----------------
__global__ __launch_bounds__(256)
void scan_mid_kernel(){
    int i = blockIdx.x*256 + threadIdx.x;
    if (i >= CHST4) return;
    float4 carry = make_float4(0.f, 0.f, 0.f, 0.f);
#pragma unroll
    for (int c = 0; c < NCHK; c++){
        float4 ap = g_aprod4[c*CHST4 + i];
        float4 he = g_hend4[c*CHST4 + i];
        g_h04[c*CHST4 + i] = carry;
        carry.x = ap.x*carry.x + he.x;
        carry.y = ap.y*carry.y + he.y;
        carry.z = ap.z*carry.z + he.z;
        carry.w = ap.w*carry.w + he.w;
    }
}

// ---------------- chunked scan pass B: correction (chunks 1..15) ----------------
template<bool FAST>
__device__ __forceinline__ void scanB_loop(
    const float (*s_dt)[32], const float (*s_c)[16], const __half (*s_y)[32],
    const __half (*s_sz)[32],
    int col, int sq, const float* a2, float4& q, size_t rowbase)
{
#pragma unroll 4
    for (int tt = 0; tt < CLEN; tt++){
        float dt = s_dt[tt][col];
        float dA0, dA1, dA2, dA3;
        if (FAST){
            float r = fx2(-dt*LOG2E);
            dA0 = fx2(dt*a2[0]);
            dA1 = dA0*r; dA2 = dA1*r; dA3 = dA2*r;
        } else {
            dA0 = fx2(dt*a2[0]); dA1 = fx2(dt*a2[1]);
            dA2 = fx2(dt*a2[2]); dA3 = fx2(dt*a2[3]);
        }
        q.x *= dA0; q.y *= dA1; q.z *= dA2; q.w *= dA3;
        float4 Cv = *reinterpret_cast<const float4*>(&s_c[tt][sq*4]);
        float yc = q.x*Cv.x + q.y*Cv.y + q.z*Cv.z + q.w*Cv.w;
        yc += __shfl_xor_sync(0xffffffffu, yc, 8);
        yc += __shfl_xor_sync(0xffffffffu, yc, 16);
        if (sq == 0){
            float y = __half2float(s_y[tt][col])
                    + yc * __half2float(s_sz[tt][col]);
            g_y16[rowbase + (size_t)tt*DINNER] = __float2half(y);
        }
    }
}

__global__ __launch_bounds__(128)
void scanB_kernel(const float* __restrict__ A_log){
    const int b = blockIdx.y, ch = blockIdx.z + 1;
    const int d0 = blockIdx.x*32;
    const int tid = threadIdx.x;
    const int lane = tid & 31;
    const int col = (tid >> 5)*8 + (lane & 7);
    const int d = d0 + col;
    const int sq = lane >> 3;
    const int t0 = ch*CLEN;

    __shared__ __align__(16) float  s_dt[CLEN][32];
    __shared__ __align__(16) float  s_c [CLEN][16];
    __shared__ __align__(16) __half s_y [CLEN][32];
    __shared__ __align__(16) __half s_sz[CLEN][32];

    for (int i = tid; i < CLEN*8; i += 128){
        int tt = i >> 3, p = (i & 7) << 2;
        size_t g = ((size_t)(b*LL + t0 + tt))*DINNER + d0 + p;
        CP_ASYNC16(smem_u32(&s_dt[tt][p]), g_dt + g);
    }
    for (int i = tid; i < CLEN*4; i += 128){
        int tt = i >> 2;
        {
            int p = (i & 3) << 2;
            size_t gb = ((size_t)(b*LL + t0 + tt))*64 + DTRANK + 16 + p;
            CP_ASYNC16(smem_u32(&s_c[tt][p]), g_xdbl + gb);
        }
        {
            int p = (i & 3) << 3;
            size_t g = ((size_t)(b*LL + t0 + tt))*DINNER + d0 + p;
            CP_ASYNC16(smem_u32(&s_y [tt][p]), g_y16  + g);
            CP_ASYNC16(smem_u32(&s_sz[tt][p]), g_sz16 + g);
        }
    }
    CP_COMMIT(); CP_WAIT(0);
    __syncthreads();

    float a2[4];
    bool fast = true;
#pragma unroll
    for (int k = 0; k < 4; k++){
        float av = expf(A_log[d*DSTATE + sq*4 + k]);
        a2[k] = -av * LOG2E;
        if (fabsf(av - (float)(sq*4 + k + 1)) > 1e-3f) fast = false;
    }
    float4 q = g_h04[ch*CHST4 + (b*DINNER + d)*4 + sq];

    size_t rowbase = ((size_t)(b*LL + t0))*DINNER + d;
    if (fast) scanB_loop<true >(s_dt, s_c, s_y, s_sz, col, sq, a2, q, rowbase);
    else      scanB_loop<false>(s_dt, s_c, s_y, s_sz, col, sq, a2, q, rowbase);
}

// ---------------- final layernorm ----------------
__global__ __launch_bounds__(128)
void ln_kernel(const float* __restrict__ gamma, const float* __restrict__ beta,
               float* __restrict__ out){
    const int m = blockIdx.x;
    const int tid = threadIdx.x;
    const float4 v = reinterpret_cast<const float4*>(g_h + (size_t)m*DMODEL)[tid];
    float s  = v.x + v.y + v.z + v.w;
    float sq = v.x*v.x + v.y*v.y + v.z*v.z + v.w*v.w;
#pragma unroll
    for (int off = 16; off; off >>= 1){
        s  += __shfl_xor_sync(0xffffffffu, s,  off);
        sq += __shfl_xor_sync(0xffffffffu, sq, off);
    }
    __shared__ float r1[4], r2[4];
    if ((tid & 31) == 0){ r1[tid>>5] = s; r2[tid>>5] = sq; }
    __syncthreads();
    s  = r1[0] + r1[1] + r1[2] + r1[3];
    sq = r2[0] + r2[1] + r2[2] + r2[3];
    float mu  = s * (1.f/DMODEL);
    float var = sq * (1.f/DMODEL) - mu*mu;
    float rs  = rsqrtf(var + 1e-5f);
    float4 g4 = reinterpret_cast<const float4*>(gamma)[tid];
    float4 b4 = reinterpret_cast<const float4*>(beta)[tid];
    float4 o;
    o.x = (v.x - mu)*rs*g4.x + b4.x;
    o.y = (v.y - mu)*rs*g4.y + b4.y;
    o.z = (v.z - mu)*rs*g4.z + b4.z;
    o.w = (v.w - mu)*rs*g4.w + b4.w;
    reinterpret_cast<float4*>(out + (size_t)m*DMODEL)[tid] = o;
}

// ---------------- launch ----------------
extern "C" void kernel_launch(void* const* d_in, const int* in_sizes, int n_in,
                              void* d_out, int out_size){
    const float* x       = (const float*)d_in[0];
    const float* in_w    = (const float*)d_in[1];
    const float* in_b    = (const float*)d_in[2];
    const float* W_xz    = (const float*)d_in[3];
    const float* conv_w  = (const float*)d_in[4];
    const float* conv_b  = (const float*)d_in[5];
    const float* W_xp    = (const float*)d_in[6];
    const float* W_dt    = (const float*)d_in[7];
    const float* b_dt    = (const float*)d_in[8];
    const float* A_log   = (const float*)d_in[9];
    const float* D_param = (const float*)d_in[10];
    const float* W_out   = (const float*)d_in[11];
    const float* ln_g    = (const float*)d_in[12];
    const float* ln_b    = (const float*)d_in[13];
    float* out = (float*)d_out;

    float *ph, *pxz, *pdt, *ppart;
    __half *ph16, *pu16, *py16, *pdtlr16, *pw16, *psz16;
    cudaGetSymbolAddress((void**)&ph,     g_h);
    cudaGetSymbolAddress((void**)&pxz,    g_xz);
    cudaGetSymbolAddress((void**)&pdt,    g_dt);
    cudaGetSymbolAddress((void**)&ppart,  g_part);
    cudaGetSymbolAddress((void**)&ph16,   g_h16);
    cudaGetSymbolAddress((void**)&pu16,   g_u16);
    cudaGetSymbolAddress((void**)&py16,   g_y16);
    cudaGetSymbolAddress((void**)&pdtlr16,g_dtlr16);
    cudaGetSymbolAddress((void**)&pw16,   g_w16);
    cudaGetSymbolAddress((void**)&psz16,  g_sz16);

    const int SMW  = 4*(2*128*80);
    const int SM128 = 4*(128*80 + 128*80);
    const int SM64  = 4*(128*80 + 64*80);
    cudaFuncSetAttribute(gemm_w64<2>, cudaFuncAttributeMaxDynamicSharedMemorySize, SMW);
    cudaFuncSetAttribute(gemm_w64<3>, cudaFuncAttributeMaxDynamicSharedMemorySize, SMW);
    cudaFuncSetAttribute(gemm_w64<4>, cudaFuncAttributeMaxDynamicSharedMemorySize, SMW);
    cudaFuncSetAttribute(gemm_h<128,1>, cudaFuncAttributeMaxDynamicSharedMemorySize, SM128);
    cudaFuncSetAttribute(gemm_h<64,0>,  cudaFuncAttributeMaxDynamicSharedMemorySize, SM64);

    const dim3 SCANA_GRID(DINNER/32, BB, NCHK);
    const dim3 SCANB_GRID(DINNER/32, BB, NCHK-1);

    // slot 4 (ncu capture) = xz GEMM (split epilogue)
    inproj_kernel<<<(MROWS*DMODEL)/128, 128>>>(x, in_w, in_b);                                   // 1
    f2h_kernel<<<(NDEPTH*SZ_XZ_L/4 + 255)/256, 256>>>(W_xz,  pw16 + OFF_XZ,  NDEPTH*SZ_XZ_L/4); // 2
    f2h_kernel<<<(NDEPTH*SZ_XP_L/4 + 255)/256, 256>>>(W_xp,  pw16 + OFF_XP,  NDEPTH*SZ_XP_L/4); // 3

    // 4 — PROFILED: xz GEMM layer 0 (EPI=4 split: xc fp32 ldc=1024, z->silu->sz16)
    gemm_w64<4><<<dim3(2048/128, MROWS/128), 128, SMW>>>(
        ph16, pw16 + OFF_XZ, pxz,
        DMODEL, DMODEL, DMODEL, DINNER, psz16, DINNER);

    conv_silu_kernel<<<((MROWS/4)*(DINNER/4))/256, 256>>>(conv_w, conv_b);                       // 5
    f2h_kernel<<<(NDEPTH*SZ_DT_L/4 + 255)/256, 256>>>(W_dt,  pw16 + OFF_DT,  NDEPTH*SZ_DT_L/4); // 6
    f2h_kernel<<<(NDEPTH*SZ_OUT_L/4 + 255)/256, 256>>>(W_out, pw16 + OFF_OUT, NDEPTH*SZ_OUT_L/4);//7

    for (int lyr = 0; lyr < NDEPTH; lyr++){
        if (lyr > 0){
            gemm_w64<4><<<dim3(2048/128, MROWS/128), 128, SMW>>>(
                ph16, pw16 + OFF_XZ + (size_t)lyr*SZ_XZ_L, pxz,
                DMODEL, DMODEL, DMODEL, DINNER, psz16, DINNER);
            conv_silu_kernel<<<((MROWS/4)*(DINNER/4))/256, 256>>>(
                conv_w + (size_t)lyr*DINNER*DCONV, conv_b + (size_t)lyr*DINNER);
        }

        gemm_h<64,0><<<dim3(1, MROWS/128, 4), 256, SM64>>>(
            pu16, pw16 + OFF_XP + (size_t)lyr*SZ_XP_L, ppart,
            DINNER, DINNER, DINNER, 64, nullptr, MROWS*64);

        reduce_xp_kernel<<<(MROWS*64)/256, 256>>>();

        gemm_h<128,1><<<dim3(DINNER/128, MROWS/128, 1), 256, SM128>>>(
            pdtlr16, pw16 + OFF_DT + (size_t)lyr*SZ_DT_L, pdt,
            DTRANK, DTRANK, DTRANK, DINNER, b_dt + (size_t)lyr*DINNER, 0);

        scanA_kernel<<<SCANA_GRID, 128>>>(
            A_log + (size_t)lyr*DINNER*DSTATE, D_param + (size_t)lyr*DINNER);
        scan_mid_kernel<<<(CHST4 + 255)/256, 256>>>();
        scanB_kernel<<<SCANB_GRID, 128>>>(
            A_log + (size_t)lyr*DINNER*DSTATE);

        if (lyr < NDEPTH-1){
            gemm_w64<3><<<dim3(DMODEL/128, MROWS/128), 128, SMW>>>(
                py16, pw16 + OFF_OUT + (size_t)lyr*SZ_OUT_L, nullptr,
                DINNER, DINNER, DINNER, 0, ph16, DMODEL);
        } else {
            gemm_w64<2><<<dim3(DMODEL/128, MROWS/128), 128, SMW>>>(
                py16, pw16 + OFF_OUT + (size_t)lyr*SZ_OUT_L, ph,
                DINNER, DINNER, DINNER, DMODEL, ph16, DMODEL);
        }
    }

    ln_kernel<<<MROWS, 128>>>(ln_g, ln_b, out);
}

// round 15
// speedup vs baseline: 1.0113x; 1.0113x over previous
#include <cuda_runtime.h>
#include <cuda_fp16.h>
#include <cstdio>
#include <cstdint>

#define BB 4
#define LL 1024
#define DIN 8
#define DMODEL 512
#define NDEPTH 4
#define DINNER 1024
#define DSTATE 16
#define DCONV 4
#define DTRANK 32
#define MROWS (BB*LL)   /* 4096 */

#define CLEN 64
#define NCHK 16
#define CHST4 (BB*DINNER*DSTATE/4)   /* 16384 float4 per chunk */

// ---------------- scratch ----------------
__device__ float  g_h[MROWS*DMODEL];
__device__ float  g_xz[MROWS*2*DINNER];
__device__ float  g_xdbl[MROWS*64];
__device__ float  g_dt[MROWS*DINNER];
__device__ float  g_part[4*MROWS*64];
__device__ float4 g_hend4[NCHK*CHST4];
__device__ float4 g_aprod4[NCHK*CHST4];

__device__ __half g_h16[MROWS*DMODEL];
__device__ __half g_u16[MROWS*DINNER];
__device__ __half g_sz16[MROWS*DINNER];
__device__ __half g_y16[MROWS*DINNER];
__device__ __half g_dtlr16[MROWS*DTRANK];
__device__ __half g_w16[6684672];

#define OFF_XZ  0
#define SZ_XZ_L (2048*512)
#define OFF_XP  4194304
#define SZ_XP_L (64*1024)
#define OFF_DT  4456448
#define SZ_DT_L (1024*32)
#define OFF_OUT 4587520
#define SZ_OUT_L (512*1024)

#define LOG2E 1.4426950408889634f

// ---------------- helpers ----------------
__device__ __forceinline__ float fx2(float x){ float y; asm("ex2.approx.f32 %0,%1;" : "=f"(y) : "f"(x)); return y; }
__device__ __forceinline__ float fexp(float x){ return fx2(x*LOG2E); }
__device__ __forceinline__ float fsilu(float x){ return x/(1.f+fexp(-x)); }
__device__ __forceinline__ uint32_t smem_u32(const void* p){
    uint32_t a; asm("{ .reg .u64 t; cvta.to.shared.u64 t, %1; cvt.u32.u64 %0, t; }" : "=r"(a) : "l"(p));
    return a;
}

#define LDSM4(r0,r1,r2,r3,addr) \
    asm volatile("ldmatrix.sync.aligned.m8n8.x4.shared.b16 {%0,%1,%2,%3}, [%4];" \
        : "=r"(r0),"=r"(r1),"=r"(r2),"=r"(r3) : "r"(addr))

#define MMA16816(d, a, b) \
    asm volatile("mma.sync.aligned.m16n8k16.row.col.f32.f16.f16.f32 " \
        "{%0,%1,%2,%3}, {%4,%5,%6,%7}, {%8,%9}, {%0,%1,%2,%3};" \
        : "+f"((d)[0]), "+f"((d)[1]), "+f"((d)[2]), "+f"((d)[3]) \
        : "r"((a)[0]), "r"((a)[1]), "r"((a)[2]), "r"((a)[3]), \
          "r"((b)[0]), "r"((b)[1]))

#define CP_ASYNC16(saddr, gptr) \
    asm volatile("cp.async.cg.shared.global [%0], [%1], 16;" :: "r"(saddr), "l"(gptr))
#define CP_COMMIT() asm volatile("cp.async.commit_group;")
#define CP_WAIT(n)  asm volatile("cp.async.wait_group %0;" :: "n"(n))

// ---------------- fp32 -> fp16 conversion ----------------
__global__ void f2h_kernel(const float* __restrict__ s, __half* __restrict__ d, int n4){
    int i = blockIdx.x*blockDim.x + threadIdx.x;
    if (i >= n4) return;
    float4 v = reinterpret_cast<const float4*>(s)[i];
    __half2* o = reinterpret_cast<__half2*>(d);
    o[2*i]   = __floats2half2_rn(v.x, v.y);
    o[2*i+1] = __floats2half2_rn(v.z, v.w);
}

// ---------------- input projection ----------------
__global__ void inproj_kernel(const float* __restrict__ x, const float* __restrict__ w,
                              const float* __restrict__ b){
    int idx = blockIdx.x*blockDim.x + threadIdx.x;
    if (idx >= MROWS*DMODEL) return;
    int m = idx / DMODEL, d = idx % DMODEL;
    const float* xr = x + m*DIN;
    const float* wr = w + d*DIN;
    float acc = b[d];
#pragma unroll
    for (int i = 0; i < DIN; i++) acc += xr[i]*wr[i];
    g_h16[idx] = __float2half(acc);
}

// ---------------- fp16 NT GEMM, 64x64 warp tiles (xz / out) ----------------
// EPI: 0 fp32 only | 2 fp32 + fp16 | 3 fp16 only
template<int EPI>
__global__ __launch_bounds__(128, 2)
void gemm_w64(const __half* __restrict__ A, const __half* __restrict__ B, float* __restrict__ C,
              int K, int lda, int ldb, int ldc, __half* __restrict__ C16, int ldc16)
{
    constexpr int BK = 32, STG = 4, ROWB = 80;
    constexpr int ABYTES = 128*ROWB;
    constexpr int STGB = 2*ABYTES;

    extern __shared__ char smem[];
    const uint32_t sb = smem_u32(smem);
    const int tid = threadIdx.x, wid = tid >> 5, lane = tid & 31;
    const int wm = wid & 1, wn = wid >> 1;
    const int row0 = blockIdx.y*128, col0 = blockIdx.x*128;
    const int ntiles = K / BK;

    const __half* Ag = A + (size_t)row0*lda;
    const __half* Bg = B + (size_t)col0*ldb;

    float acc[4][8][4];
#pragma unroll
    for (int i = 0; i < 4; i++)
#pragma unroll
        for (int j = 0; j < 8; j++)
#pragma unroll
            for (int q = 0; q < 4; q++) acc[i][j][q] = 0.f;

    auto issue = [&](int t){
        int buf = t & (STG-1);
        uint32_t as = sb + buf*STGB;
        uint32_t bs = as + ABYTES;
        int kt = t*BK;
#pragma unroll
        for (int it = 0; it < 4; it++){
            int i = it*128 + tid;
            int r = i >> 2, c = i & 3;
            CP_ASYNC16(as + r*ROWB + c*16, Ag + (size_t)r*lda + kt + c*8);
        }
#pragma unroll
        for (int it = 0; it < 4; it++){
            int i = it*128 + tid;
            int r = i >> 2, c = i & 3;
            CP_ASYNC16(bs + r*ROWB + c*16, Bg + (size_t)r*ldb + kt + c*8);
        }
        CP_COMMIT();
    };

    auto compute = [&](int t){
        int buf = t & (STG-1);
        uint32_t as = sb + buf*STGB + wm*64*ROWB;
        uint32_t bs = sb + buf*STGB + ABYTES + wn*64*ROWB;
#pragma unroll
        for (int s = 0; s < 2; s++){
            uint32_t a[4][4];
#pragma unroll
            for (int im = 0; im < 4; im++){
                uint32_t addr = as + (im*16 + (lane & 7) + ((lane >> 3) & 1)*8)*ROWB
                              + (2*s + (lane >> 4))*16;
                LDSM4(a[im][0], a[im][1], a[im][2], a[im][3], addr);
            }
            uint32_t b[8][2];
#pragma unroll
            for (int j = 0; j < 4; j++){
                uint32_t addr = bs + (j*16 + (lane & 7) + (lane >> 4)*8)*ROWB
                              + (2*s + ((lane >> 3) & 1))*16;
                LDSM4(b[2*j][0], b[2*j][1], b[2*j+1][0], b[2*j+1][1], addr);
            }
#pragma unroll
            for (int im = 0; im < 4; im++)
#pragma unroll
                for (int j = 0; j < 8; j++)
                    MMA16816(acc[im][j], a[im], b[j]);
        }
    };

#pragma unroll
    for (int i = 0; i < STG-1; i++)
        if (i < ntiles) issue(i);

    for (int t = 0; t < ntiles; t++){
        int rem = ntiles - 1 - t;
        if (rem >= 2)      { CP_WAIT(2); }
        else if (rem == 1) { CP_WAIT(1); }
        else               { CP_WAIT(0); }
        __syncthreads();
        if (t + STG-1 < ntiles) issue(t + STG-1);
        compute(t);
    }

#pragma unroll
    for (int im = 0; im < 4; im++){
        int r = row0 + wm*64 + im*16 + (lane >> 2);
#pragma unroll
        for (int j = 0; j < 8; j++){
            int c = col0 + wn*64 + j*8 + (lane & 3)*2;
            float v0 = acc[im][j][0], v1 = acc[im][j][1];
            float v2 = acc[im][j][2], v3 = acc[im][j][3];
            if (EPI != 3){
                *reinterpret_cast<float2*>(&C[(size_t)r*ldc + c])     = make_float2(v0, v1);
                *reinterpret_cast<float2*>(&C[(size_t)(r+8)*ldc + c]) = make_float2(v2, v3);
            }
            if (EPI == 2 || EPI == 3){
                *reinterpret_cast<__half2*>(&C16[(size_t)r*ldc16 + c])     = __floats2half2_rn(v0, v1);
                *reinterpret_cast<__half2*>(&C16[(size_t)(r+8)*ldc16 + c]) = __floats2half2_rn(v2, v3);
            }
        }
    }
}

// ---------------- fp16 NT GEMM, 256 threads (xp split-K / dt) ----------------
template<int BN, int EPI>
__global__ __launch_bounds__(256, 2)
void gemm_h(const __half* __restrict__ A, const __half* __restrict__ B, float* __restrict__ C,
            int K, int lda, int ldb, int ldc, const float* __restrict__ bias,
            int partStride)
{
    constexpr int BM = 128, BK = 32, STG = 4;
    constexpr int NW  = BN/2;
    constexpr int NFR = NW/8;
    constexpr int ROWB = 80;
    constexpr int ABYTES = BM*ROWB;
    constexpr int BBYTES = BN*ROWB;
    constexpr int STGB = ABYTES + BBYTES;

    extern __shared__ char smem[];
    const uint32_t sb = smem_u32(smem);
    const int tid = threadIdx.x, wid = tid >> 5, lane = tid & 31;
    const int wm = wid & 3, wn = wid >> 2;
    const int row0 = blockIdx.y*BM, col0 = blockIdx.x*BN;
    const int kslice = K / gridDim.z;
    const int k0 = blockIdx.z * kslice;
    const int ntiles = kslice / BK;

    const __half* Ag = A + (size_t)row0*lda + k0;
    const __half* Bg = B + (size_t)col0*ldb + k0;
    float* Cp = C + (size_t)blockIdx.z * partStride;

    float acc[2][NFR][4];
#pragma unroll
    for (int i = 0; i < 2; i++)
#pragma unroll
        for (int j = 0; j < NFR; j++)
#pragma unroll
            for (int q = 0; q < 4; q++) acc[i][j][q] = 0.f;

    auto issue = [&](int t){
        int buf = t & (STG-1);
        uint32_t as = sb + buf*STGB;
        uint32_t bs = as + ABYTES;
        int kt = t*BK;
#pragma unroll
        for (int it = 0; it < 2; it++){
            int i = it*256 + tid;
            int r = i >> 2, c = i & 3;
            CP_ASYNC16(as + r*ROWB + c*16, Ag + (size_t)r*lda + kt + c*8);
        }
#pragma unroll
        for (int it = 0; it < BN/64; it++){
            int i = it*256 + tid;
            int r = i >> 2, c = i & 3;
            CP_ASYNC16(bs + r*ROWB + c*16, Bg + (size_t)r*ldb + kt + c*8);
        }
        CP_COMMIT();
    };

    auto compute = [&](int t){
        int buf = t & (STG-1);
        uint32_t as = sb + buf*STGB + wm*32*ROWB;
        uint32_t bs = sb + buf*STGB + ABYTES + wn*NW*ROWB;
#pragma unroll
        for (int s = 0; s < 2; s++){
            uint32_t a[2][4];
#pragma unroll
            for (int im = 0; im < 2; im++){
                uint32_t addr = as + (im*16 + (lane & 7) + ((lane >> 3) & 1)*8)*ROWB
                              + (2*s + (lane >> 4))*16;
                LDSM4(a[im][0], a[im][1], a[im][2], a[im][3], addr);
            }
            uint32_t b[NFR][2];
#pragma unroll
            for (int j = 0; j < NFR/2; j++){
                uint32_t addr = bs + (j*16 + (lane & 7) + (lane >> 4)*8)*ROWB
                              + (2*s + ((lane >> 3) & 1))*16;
                LDSM4(b[2*j][0], b[2*j][1], b[2*j+1][0], b[2*j+1][1], addr);
            }
#pragma unroll
            for (int im = 0; im < 2; im++)
#pragma unroll
                for (int j = 0; j < NFR; j++)
                    MMA16816(acc[im][j], a[im], b[j]);
        }
    };

#pragma unroll
    for (int i = 0; i < STG-1; i++)
        if (i < ntiles) issue(i);

    for (int t = 0; t < ntiles; t++){
        int rem = ntiles - 1 - t;
        if (rem >= 2)      { CP_WAIT(2); }
        else if (rem == 1) { CP_WAIT(1); }
        else               { CP_WAIT(0); }
        __syncthreads();
        if (t + STG-1 < ntiles) issue(t + STG-1);
        compute(t);
    }

#pragma unroll
    for (int im = 0; im < 2; im++){
        int r = row0 + wm*32 + im*16 + (lane >> 2);
#pragma unroll
        for (int j = 0; j < NFR; j++){
            int c = col0 + wn*NW + j*8 + (lane & 3)*2;
            float v0 = acc[im][j][0], v1 = acc[im][j][1];
            float v2 = acc[im][j][2], v3 = acc[im][j][3];
            if (EPI == 1){
                float b0 = bias[c], b1 = bias[c+1];
                v0 += b0; v1 += b1; v2 += b0; v3 += b1;
                v0 = (v0 > 20.f) ? v0 : log1pf(fexp(v0));
                v1 = (v1 > 20.f) ? v1 : log1pf(fexp(v1));
                v2 = (v2 > 20.f) ? v2 : log1pf(fexp(v2));
                v3 = (v3 > 20.f) ? v3 : log1pf(fexp(v3));
            }
            *reinterpret_cast<float2*>(&Cp[(size_t)r*ldc + c])     = make_float2(v0, v1);
            *reinterpret_cast<float2*>(&Cp[(size_t)(r+8)*ldc + c]) = make_float2(v2, v3);
        }
    }
}

// ---------------- split-K reduce for xp gemm ----------------
__global__ void reduce_xp_kernel(){
    int idx = blockIdx.x*blockDim.x + threadIdx.x;
    if (idx >= MROWS*64) return;
    float s = g_part[idx] + g_part[MROWS*64 + idx]
            + g_part[2*MROWS*64 + idx] + g_part[3*MROWS*64 + idx];
    g_xdbl[idx] = s;
    int col = idx & 63;
    if (col < DTRANK){
        int row = idx >> 6;
        g_dtlr16[row*DTRANK + col] = __float2half(s);
    }
}

// ---------------- causal conv1d + silu (4 ch x 8 t / thread) ----------------
__global__ __launch_bounds__(256)
void conv_silu_kernel(const float* __restrict__ cw, const float* __restrict__ cb){
    int idx = blockIdx.x*blockDim.x + threadIdx.x;
    if (idx >= (MROWS/8)*(DINNER/4)) return;
    int rg = idx >> 8;                 // 0..511
    int e  = (idx & 255) << 2;
    int b  = rg >> 7;                  // LL/8 = 128 groups per batch
    int l0 = (rg & 127) << 3;

    float cwa[4][4];
#pragma unroll
    for (int j = 0; j < 4; j++)
        *reinterpret_cast<float4*>(cwa[j]) =
            *reinterpret_cast<const float4*>(cw + (size_t)(e+j)*DCONV);
    float4 bias = *reinterpret_cast<const float4*>(cb + e);

    float4 xv[11];
#pragma unroll
    for (int k = 0; k < 11; k++){
        int lp = l0 - 3 + k;
        if (lp >= 0)
            xv[k] = *reinterpret_cast<const float4*>(
                g_xz + (size_t)(b*LL + lp)*(2*DINNER) + e);
        else
            xv[k] = make_float4(0.f, 0.f, 0.f, 0.f);
    }

#pragma unroll
    for (int t = 0; t < 8; t++){
        float4 acc = bias;
#pragma unroll
        for (int k = 0; k < 4; k++){
            float4 xc = xv[t + k];
            acc.x += cwa[0][k]*xc.x;
            acc.y += cwa[1][k]*xc.y;
            acc.z += cwa[2][k]*xc.z;
            acc.w += cwa[3][k]*xc.w;
        }
        int r = b*LL + l0 + t;
        size_t o = (size_t)r*DINNER + e;
        __half2 u01 = __floats2half2_rn(fsilu(acc.x), fsilu(acc.y));
        __half2 u23 = __floats2half2_rn(fsilu(acc.z), fsilu(acc.w));
        uint2 pk;
        pk.x = *reinterpret_cast<uint32_t*>(&u01);
        pk.y = *reinterpret_cast<uint32_t*>(&u23);
        *reinterpret_cast<uint2*>(g_u16 + o) = pk;

        float4 z = *reinterpret_cast<const float4*>(
            g_xz + (size_t)r*(2*DINNER) + DINNER + e);
        __half2 s01 = __floats2half2_rn(fsilu(z.x), fsilu(z.y));
        __half2 s23 = __floats2half2_rn(fsilu(z.z), fsilu(z.w));
        uint2 pk2;
        pk2.x = *reinterpret_cast<uint32_t*>(&s01);
        pk2.y = *reinterpret_cast<uint32_t*>(&s23);
        *reinterpret_cast<uint2*>(g_sz16 + o) = pk2;
    }
}

// ---------------- chunked scan pass A ----------------
template<bool FAST>
__device__ __forceinline__ void scanA_loop(
    const float (*s_dt)[32], const float (*s_bc)[32], const __half (*s_u)[32],
    const __half (*s_sz)[32],
    int col, int sq, const float* a2, float* st, float& sdt, float dp, size_t rowbase)
{
#pragma unroll 4
    for (int tt = 0; tt < CLEN; tt++){
        float dt = s_dt[tt][col];
        float uu = __half2float(s_u[tt][col]);
        float du = dt*uu;
        float4 Bv = *reinterpret_cast<const float4*>(&s_bc[tt][sq*4]);
        float4 Cv = *reinterpret_cast<const float4*>(&s_bc[tt][16 + sq*4]);
        float dA0, dA1, dA2, dA3;
        if (FAST){
            float r = fx2(-dt*LOG2E);
            dA0 = fx2(dt*a2[0]);
            dA1 = dA0*r; dA2 = dA1*r; dA3 = dA2*r;
        } else {
            dA0 = fx2(dt*a2[0]); dA1 = fx2(dt*a2[1]);
            dA2 = fx2(dt*a2[2]); dA3 = fx2(dt*a2[3]);
        }
        st[0] = dA0*st[0] + Bv.x*du;
        st[1] = dA1*st[1] + Bv.y*du;
        st[2] = dA2*st[2] + Bv.z*du;
        st[3] = dA3*st[3] + Bv.w*du;
        sdt += dt;
        float y = st[0]*Cv.x + st[1]*Cv.y + st[2]*Cv.z + st[3]*Cv.w;
        y += __shfl_xor_sync(0xffffffffu, y, 8);
        y += __shfl_xor_sync(0xffffffffu, y, 16);
        if (sq == 0){
            float yo = (y + uu*dp) * __half2float(s_sz[tt][col]);
            g_y16[rowbase + (size_t)tt*DINNER] = __float2half(yo);
        }
    }
}

__global__ __launch_bounds__(128)
void scanA_kernel(const float* __restrict__ A_log, const float* __restrict__ Dp){
    const int b = blockIdx.y, ch = blockIdx.z;
    const int d0 = blockIdx.x*32;
    const int tid = threadIdx.x;
    const int lane = tid & 31;
    const int col = (tid >> 5)*8 + (lane & 7);
    const int d = d0 + col;
    const int sq = lane >> 3;
    const int t0 = ch*CLEN;

    __shared__ __align__(16) float  s_dt[CLEN][32];
    __shared__ __align__(16) float  s_bc[CLEN][32];
    __shared__ __align__(16) __half s_u [CLEN][32];
    __shared__ __align__(16) __half s_sz[CLEN][32];

    for (int i = tid; i < CLEN*8; i += 128){
        int tt = i >> 3, p = (i & 7) << 2;
        size_t g = ((size_t)(b*LL + t0 + tt))*DINNER + d0 + p;
        CP_ASYNC16(smem_u32(&s_dt[tt][p]), g_dt + g);
        size_t gb = ((size_t)(b*LL + t0 + tt))*64 + DTRANK + p;
        CP_ASYNC16(smem_u32(&s_bc[tt][p]), g_xdbl + gb);
    }
    for (int i = tid; i < CLEN*4; i += 128){
        int tt = i >> 2, p = (i & 3) << 3;
        size_t g = ((size_t)(b*LL + t0 + tt))*DINNER + d0 + p;
        CP_ASYNC16(smem_u32(&s_u [tt][p]), g_u16  + g);
        CP_ASYNC16(smem_u32(&s_sz[tt][p]), g_sz16 + g);
    }
    CP_COMMIT(); CP_WAIT(0);
    __syncthreads();

    float a2[4];
    bool fast = true;
#pragma unroll
    for (int k = 0; k < 4; k++){
        float av = expf(A_log[d*DSTATE + sq*4 + k]);
        a2[k] = -av * LOG2E;
        if (fabsf(av - (float)(sq*4 + k + 1)) > 1e-3f) fast = false;
    }
    const float dp = Dp[d];

    float st[4] = {0.f, 0.f, 0.f, 0.f};
    float sdt = 0.f;
    size_t rowbase = ((size_t)(b*LL + t0))*DINNER + d;
    if (fast) scanA_loop<true >(s_dt, s_bc, s_u, s_sz, col, sq, a2, st, sdt, dp, rowbase);
    else      scanA_loop<false>(s_dt, s_bc, s_u, s_sz, col, sq, a2, st, sdt, dp, rowbase);

    float4 he = make_float4(st[0], st[1], st[2], st[3]);
    float4 ap;
    ap.x = fx2(sdt*a2[0]); ap.y = fx2(sdt*a2[1]);
    ap.z = fx2(sdt*a2[2]); ap.w = fx2(sdt*a2[3]);
    int ci = ch*CHST4 + (b*DINNER + d)*4 + sq;
    g_hend4[ci]  = he;
    g_aprod4[ci] = ap;
}

// ---------------- chunked scan pass B: inline prefix + correction (chunks 1..15) ----------------
template<bool FAST>
__device__ __forceinline__ void scanB_loop(
    const float (*s_dt)[32], const float (*s_c)[16], const __half (*s_y)[32],
    const __half (*s_sz)[32],
    int col, int sq, const float* a2, float4& q, size_t rowbase)
{
#pragma unroll 4
    for (int tt = 0; tt < CLEN; tt++){
        float dt = s_dt[tt][col];
        float dA0, dA1, dA2, dA3;
        if (FAST){
            float r = fx2(-dt*LOG2E);
            dA0 = fx2(dt*a2[0]);
            dA1 = dA0*r; dA2 = dA1*r; dA3 = dA2*r;
        } else {
            dA0 = fx2(dt*a2[0]); dA1 = fx2(dt*a2[1]);
            dA2 = fx2(dt*a2[2]); dA3 = fx2(dt*a2[3]);
        }
        q.x *= dA0; q.y *= dA1; q.z *= dA2; q.w *= dA3;
        float4 Cv = *reinterpret_cast<const float4*>(&s_c[tt][sq*4]);
        float yc = q.x*Cv.x + q.y*Cv.y + q.z*Cv.z + q.w*Cv.w;
        yc += __shfl_xor_sync(0xffffffffu, yc, 8);
        yc += __shfl_xor_sync(0xffffffffu, yc, 16);
        if (sq == 0){
            float y = __half2float(s_y[tt][col])
                    + yc * __half2float(s_sz[tt][col]);
            g_y16[rowbase + (size_t)tt*DINNER] = __float2half(y);
        }
    }
}

__global__ __launch_bounds__(128)
void scanB_kernel(const float* __restrict__ A_log){
    const int b = blockIdx.y, ch = blockIdx.z + 1;   // chunk 0 needs no correction
    const int d0 = blockIdx.x*32;
    const int tid = threadIdx.x;
    const int lane = tid & 31;
    const int col = (tid >> 5)*8 + (lane & 7);
    const int d = d0 + col;
    const int sq = lane >> 3;
    const int t0 = ch*CLEN;

    __shared__ __align__(16) float  s_dt[CLEN][32];
    __shared__ __align__(16) float  s_c [CLEN][16];
    __shared__ __align__(16) __half s_y [CLEN][32];
    __shared__ __align__(16) __half s_sz[CLEN][32];

    for (int i = tid; i < CLEN*8; i += 128){
        int tt = i >> 3, p = (i & 7) << 2;
        size_t g = ((size_t)(b*LL + t0 + tt))*DINNER + d0 + p;
        CP_ASYNC16(smem_u32(&s_dt[tt][p]), g_dt + g);
    }
    for (int i = tid; i < CLEN*4; i += 128){
        int tt = i >> 2;
        {
            int p = (i & 3) << 2;
            size_t gb = ((size_t)(b*LL + t0 + tt))*64 + DTRANK + 16 + p;
            CP_ASYNC16(smem_u32(&s_c[tt][p]), g_xdbl + gb);
        }
        {
            int p = (i & 3) << 3;
            size_t g = ((size_t)(b*LL + t0 + tt))*DINNER + d0 + p;
            CP_ASYNC16(smem_u32(&s_y [tt][p]), g_y16  + g);
            CP_ASYNC16(smem_u32(&s_sz[tt][p]), g_sz16 + g);
        }
    }
    CP_COMMIT();

    // chunk-prefix from L2-hot summaries while cp.async drains
    const int base = (b*DINNER + d)*4 + sq;
    float4 q = make_float4(0.f, 0.f, 0.f, 0.f);
    for (int c = 0; c < ch; c++){
        float4 ap = g_aprod4[c*CHST4 + base];
        float4 he = g_hend4[c*CHST4 + base];
        q.x = ap.x*q.x + he.x;
        q.y = ap.y*q.y + he.y;
        q.z = ap.z*q.z + he.z;
        q.w = ap.w*q.w + he.w;
    }

    float a2[4];
    bool fast = true;
#pragma unroll
    for (int k = 0; k < 4; k++){
        float av = expf(A_log[d*DSTATE + sq*4 + k]);
        a2[k] = -av * LOG2E;
        if (fabsf(av - (float)(sq*4 + k + 1)) > 1e-3f) fast = false;
    }

    CP_WAIT(0);
    __syncthreads();

    size_t rowbase = ((size_t)(b*LL + t0))*DINNER + d;
    if (fast) scanB_loop<true >(s_dt, s_c, s_y, s_sz, col, sq, a2, q, rowbase);
    else      scanB_loop<false>(s_dt, s_c, s_y, s_sz, col, sq, a2, q, rowbase);
}

// ---------------- final layernorm ----------------
__global__ __launch_bounds__(128)
void ln_kernel(const float* __restrict__ gamma, const float* __restrict__ beta,
               float* __restrict__ out){
    const int m = blockIdx.x;
    const int tid = threadIdx.x;
    const float4 v = reinterpret_cast<const float4*>(g_h + (size_t)m*DMODEL)[tid];
    float s  = v.x + v.y + v.z + v.w;
    float sq = v.x*v.x + v.y*v.y + v.z*v.z + v.w*v.w;
#pragma unroll
    for (int off = 16; off; off >>= 1){
        s  += __shfl_xor_sync(0xffffffffu, s,  off);
        sq += __shfl_xor_sync(0xffffffffu, sq, off);
    }
    __shared__ float r1[4], r2[4];
    if ((tid & 31) == 0){ r1[tid>>5] = s; r2[tid>>5] = sq; }
    __syncthreads();
    s  = r1[0] + r1[1] + r1[2] + r1[3];
    sq = r2[0] + r2[1] + r2[2] + r2[3];
    float mu  = s * (1.f/DMODEL);
    float var = sq * (1.f/DMODEL) - mu*mu;
    float rs  = rsqrtf(var + 1e-5f);
    float4 g4 = reinterpret_cast<const float4*>(gamma)[tid];
    float4 b4 = reinterpret_cast<const float4*>(beta)[tid];
    float4 o;
    o.x = (v.x - mu)*rs*g4.x + b4.x;
    o.y = (v.y - mu)*rs*g4.y + b4.y;
    o.z = (v.z - mu)*rs*g4.z + b4.z;
    o.w = (v.w - mu)*rs*g4.w + b4.w;
    reinterpret_cast<float4*>(out + (size_t)m*DMODEL)[tid] = o;
}

// ---------------- launch ----------------
extern "C" void kernel_launch(void* const* d_in, const int* in_sizes, int n_in,
                              void* d_out, int out_size){
    const float* x       = (const float*)d_in[0];
    const float* in_w    = (const float*)d_in[1];
    const float* in_b    = (const float*)d_in[2];
    const float* W_xz    = (const float*)d_in[3];
    const float* conv_w  = (const float*)d_in[4];
    const float* conv_b  = (const float*)d_in[5];
    const float* W_xp    = (const float*)d_in[6];
    const float* W_dt    = (const float*)d_in[7];
    const float* b_dt    = (const float*)d_in[8];
    const float* A_log   = (const float*)d_in[9];
    const float* D_param = (const float*)d_in[10];
    const float* W_out   = (const float*)d_in[11];
    const float* ln_g    = (const float*)d_in[12];
    const float* ln_b    = (const float*)d_in[13];
    float* out = (float*)d_out;

    float *ph, *pxz, *pdt, *ppart;
    __half *ph16, *pu16, *py16, *pdtlr16, *pw16;
    cudaGetSymbolAddress((void**)&ph,     g_h);
    cudaGetSymbolAddress((void**)&pxz,    g_xz);
    cudaGetSymbolAddress((void**)&pdt,    g_dt);
    cudaGetSymbolAddress((void**)&ppart,  g_part);
    cudaGetSymbolAddress((void**)&ph16,   g_h16);
    cudaGetSymbolAddress((void**)&pu16,   g_u16);
    cudaGetSymbolAddress((void**)&py16,   g_y16);
    cudaGetSymbolAddress((void**)&pdtlr16,g_dtlr16);
    cudaGetSymbolAddress((void**)&pw16,   g_w16);

    const int SMW  = 4*(2*128*80);
    const int SM128 = 4*(128*80 + 128*80);
    const int SM64  = 4*(128*80 + 64*80);
    cudaFuncSetAttribute(gemm_w64<0>, cudaFuncAttributeMaxDynamicSharedMemorySize, SMW);
    cudaFuncSetAttribute(gemm_w64<2>, cudaFuncAttributeMaxDynamicSharedMemorySize, SMW);
    cudaFuncSetAttribute(gemm_w64<3>, cudaFuncAttributeMaxDynamicSharedMemorySize, SMW);
    cudaFuncSetAttribute(gemm_h<128,1>, cudaFuncAttributeMaxDynamicSharedMemorySize, SM128);
    cudaFuncSetAttribute(gemm_h<64,0>,  cudaFuncAttributeMaxDynamicSharedMemorySize, SM64);

    const dim3 SCANA_GRID(DINNER/32, BB, NCHK);
    const dim3 SCANB_GRID(DINNER/32, BB, NCHK-1);

    // slot 4 (ncu capture) = conv v4 (8 timesteps/thread)
    inproj_kernel<<<(MROWS*DMODEL)/128, 128>>>(x, in_w, in_b);                                   // 1
    f2h_kernel<<<(NDEPTH*SZ_XZ_L/4 + 255)/256, 256>>>(W_xz,  pw16 + OFF_XZ,  NDEPTH*SZ_XZ_L/4); // 2

    gemm_w64<0><<<dim3(2048/128, MROWS/128), 128, SMW>>>(                                        // 3
        ph16, pw16 + OFF_XZ, pxz,
        DMODEL, DMODEL, DMODEL, 2*DINNER, nullptr, 0);

    conv_silu_kernel<<<((MROWS/8)*(DINNER/4))/256, 256>>>(conv_w, conv_b);                       // 4 PROFILED

    f2h_kernel<<<(NDEPTH*SZ_XP_L/4 + 255)/256, 256>>>(W_xp,  pw16 + OFF_XP,  NDEPTH*SZ_XP_L/4); // 5
    f2h_kernel<<<(NDEPTH*SZ_DT_L/4 + 255)/256, 256>>>(W_dt,  pw16 + OFF_DT,  NDEPTH*SZ_DT_L/4); // 6
    f2h_kernel<<<(NDEPTH*SZ_OUT_L/4 + 255)/256, 256>>>(W_out, pw16 + OFF_OUT, NDEPTH*SZ_OUT_L/4);//7

    for (int lyr = 0; lyr < NDEPTH; lyr++){
        if (lyr > 0){
            gemm_w64<0><<<dim3(2048/128, MROWS/128), 128, SMW>>>(
                ph16, pw16 + OFF_XZ + (size_t)lyr*SZ_XZ_L, pxz,
                DMODEL, DMODEL, DMODEL, 2*DINNER, nullptr, 0);
            conv_silu_kernel<<<((MROWS/8)*(DINNER/4))/256, 256>>>(
                conv_w + (size_t)lyr*DINNER*DCONV, conv_b + (size_t)lyr*DINNER);
        }

        gemm_h<64,0><<<dim3(1, MROWS/128, 4), 256, SM64>>>(
            pu16, pw16 + OFF_XP + (size_t)lyr*SZ_XP_L, ppart,
            DINNER, DINNER, DINNER, 64, nullptr, MROWS*64);

        reduce_xp_kernel<<<(MROWS*64)/256, 256>>>();

        gemm_h<128,1><<<dim3(DINNER/128, MROWS/128, 1), 256, SM128>>>(
            pdtlr16, pw16 + OFF_DT + (size_t)lyr*SZ_DT_L, pdt,
            DTRANK, DTRANK, DTRANK, DINNER, b_dt + (size_t)lyr*DINNER, 0);

        scanA_kernel<<<SCANA_GRID, 128>>>(
            A_log + (size_t)lyr*DINNER*DSTATE, D_param + (size_t)lyr*DINNER);
        scanB_kernel<<<SCANB_GRID, 128>>>(
            A_log + (size_t)lyr*DINNER*DSTATE);

        if (lyr < NDEPTH-1){
            gemm_w64<3><<<dim3(DMODEL/128, MROWS/128), 128, SMW>>>(
                py16, pw16 + OFF_OUT + (size_t)lyr*SZ_OUT_L, nullptr,
                DINNER, DINNER, DINNER, 0, ph16, DMODEL);
        } else {
            gemm_w64<2><<<dim3(DMODEL/128, MROWS/128), 128, SMW>>>(
                py16, pw16 + OFF_OUT + (size_t)lyr*SZ_OUT_L, ph,
                DINNER, DINNER, DINNER, DMODEL, ph16, DMODEL);
        }
    }

    ln_kernel<<<MROWS, 128>>>(ln_g, ln_b, out);
}

// round 17
// speedup vs baseline: 1.0937x; 1.0815x over previous
#include <cuda_runtime.h>
#include <cuda_fp16.h>
#include <cstdio>
#include <cstdint>

#define BB 4
#define LL 1024
#define DIN 8
#define DMODEL 512
#define NDEPTH 4
#define DINNER 1024
#define DSTATE 16
#define DCONV 4
#define DTRANK 32
#define MROWS (BB*LL)   /* 4096 */

// ---------------- scratch ----------------
__device__ float  g_h[MROWS*DMODEL];
__device__ float  g_xz[MROWS*2*DINNER];
__device__ float  g_u[MROWS*DINNER];
__device__ float  g_sz[MROWS*DINNER];
__device__ float  g_xdbl[MROWS*64];
__device__ float  g_dt[MROWS*DINNER];
__device__ float  g_part[4*MROWS*64];

__device__ __half g_h16[MROWS*DMODEL];
__device__ __half g_u16[MROWS*DINNER];
__device__ __half g_y16[MROWS*DINNER];
__device__ __half g_dtlr16[MROWS*DTRANK];
__device__ __half g_w16[6684672];

#define OFF_XZ  0
#define SZ_XZ_L (2048*512)
#define OFF_XP  4194304
#define SZ_XP_L (64*1024)
#define OFF_DT  4456448
#define SZ_DT_L (1024*32)
#define OFF_OUT 4587520
#define SZ_OUT_L (512*1024)

// ---------------- helpers ----------------
__device__ __forceinline__ float fx2(float x){ float y; asm("ex2.approx.f32 %0,%1;" : "=f"(y) : "f"(x)); return y; }
__device__ __forceinline__ float fexp(float x){ return fx2(x*1.4426950408889634f); }
__device__ __forceinline__ float fsilu(float x){ return x/(1.f+fexp(-x)); }
__device__ __forceinline__ uint32_t smem_u32(const void* p){
    uint32_t a; asm("{ .reg .u64 t; cvta.to.shared.u64 t, %1; cvt.u32.u64 %0, t; }" : "=r"(a) : "l"(p));
    return a;
}

#define LDSM4(r0,r1,r2,r3,addr) \
    asm volatile("ldmatrix.sync.aligned.m8n8.x4.shared.b16 {%0,%1,%2,%3}, [%4];" \
        : "=r"(r0),"=r"(r1),"=r"(r2),"=r"(r3) : "r"(addr))

#define MMA16816(d, a, b) \
    asm volatile("mma.sync.aligned.m16n8k16.row.col.f32.f16.f16.f32 " \
        "{%0,%1,%2,%3}, {%4,%5,%6,%7}, {%8,%9}, {%0,%1,%2,%3};" \
        : "+f"((d)[0]), "+f"((d)[1]), "+f"((d)[2]), "+f"((d)[3]) \
        : "r"((a)[0]), "r"((a)[1]), "r"((a)[2]), "r"((a)[3]), \
          "r"((b)[0]), "r"((b)[1]))

#define CP_ASYNC16(saddr, gptr) \
    asm volatile("cp.async.cg.shared.global [%0], [%1], 16;" :: "r"(saddr), "l"(gptr))
#define CP_COMMIT() asm volatile("cp.async.commit_group;")
#define CP_WAIT(n)  asm volatile("cp.async.wait_group %0;" :: "n"(n))

// ---------------- fp32 -> fp16 conversion ----------------
__global__ void f2h_kernel(const float* __restrict__ s, __half* __restrict__ d, int n4){
    int i = blockIdx.x*blockDim.x + threadIdx.x;
    if (i >= n4) return;
    float4 v = reinterpret_cast<const float4*>(s)[i];
    __half2* o = reinterpret_cast<__half2*>(d);
    o[2*i]   = __floats2half2_rn(v.x, v.y);
    o[2*i+1] = __floats2half2_rn(v.z, v.w);
}

// ---------------- input projection ----------------
__global__ void inproj_kernel(const float* __restrict__ x, const float* __restrict__ w,
                              const float* __restrict__ b){
    int idx = blockIdx.x*blockDim.x + threadIdx.x;
    if (idx >= MROWS*DMODEL) return;
    int m = idx / DMODEL, d = idx % DMODEL;
    const float* xr = x + m*DIN;
    const float* wr = w + d*DIN;
    float acc = b[d];
#pragma unroll
    for (int i = 0; i < DIN; i++) acc += xr[i]*wr[i];
    g_h[idx] = acc;
    g_h16[idx] = __float2half(acc);
}

// ---------------- fp16 tensor-core NT GEMM ----------------
// EPI: 0 none | 1 softplus(c+bias[n]) | 2 dual-write fp32 C + fp16 C16.
template<int BN, int EPI>
__global__ __launch_bounds__(256, 2)
void gemm_h(const __half* __restrict__ A, const __half* __restrict__ B, float* __restrict__ C,
            int K, int lda, int ldb, int ldc, const float* __restrict__ bias,
            __half* __restrict__ C16, int ldc16, int partStride)
{
    constexpr int BM = 128, BK = 32, STG = 4;
    constexpr int NW  = BN/2;
    constexpr int NFR = NW/8;
    constexpr int ROWB = 80;
    constexpr int ABYTES = BM*ROWB;
    constexpr int BBYTES = BN*ROWB;
    constexpr int STGB = ABYTES + BBYTES;

    extern __shared__ char smem[];
    const uint32_t sb = smem_u32(smem);
    const int tid = threadIdx.x, wid = tid >> 5, lane = tid & 31;
    const int wm = wid & 3, wn = wid >> 2;
    const int row0 = blockIdx.y*BM, col0 = blockIdx.x*BN;
    const int kslice = K / gridDim.z;
    const int k0 = blockIdx.z * kslice;
    const int ntiles = kslice / BK;

    const __half* Ag = A + (size_t)row0*lda + k0;
    const __half* Bg = B + (size_t)col0*ldb + k0;
    float* Cp = C + (size_t)blockIdx.z * partStride;

    float acc[2][NFR][4];
#pragma unroll
    for (int i = 0; i < 2; i++)
#pragma unroll
        for (int j = 0; j < NFR; j++)
#pragma unroll
            for (int q = 0; q < 4; q++) acc[i][j][q] = 0.f;

    auto issue = [&](int t){
        int buf = t & (STG-1);
        uint32_t as = sb + buf*STGB;
        uint32_t bs = as + ABYTES;
        int kt = t*BK;
#pragma unroll
        for (int it = 0; it < 2; it++){
            int i = it*256 + tid;
            int r = i >> 2, c = i & 3;
            CP_ASYNC16(as + r*ROWB + c*16, Ag + (size_t)r*lda + kt + c*8);
        }
#pragma unroll
        for (int it = 0; it < BN/64; it++){
            int i = it*256 + tid;
            int r = i >> 2, c = i & 3;
            CP_ASYNC16(bs + r*ROWB + c*16, Bg + (size_t)r*ldb + kt + c*8);
        }
        CP_COMMIT();
    };

    auto compute = [&](int t){
        int buf = t & (STG-1);
        uint32_t as = sb + buf*STGB + wm*32*ROWB;
        uint32_t bs = sb + buf*STGB + ABYTES + wn*NW*ROWB;
#pragma unroll
        for (int s = 0; s < 2; s++){
            uint32_t a[2][4];
#pragma unroll
            for (int im = 0; im < 2; im++){
                uint32_t addr = as + (im*16 + (lane & 7) + ((lane >> 3) & 1)*8)*ROWB
                              + (2*s + (lane >> 4))*16;
                LDSM4(a[im][0], a[im][1], a[im][2], a[im][3], addr);
            }
            uint32_t b[NFR][2];
#pragma unroll
            for (int j = 0; j < NFR/2; j++){
                uint32_t addr = bs + (j*16 + (lane & 7) + (lane >> 4)*8)*ROWB
                              + (2*s + ((lane >> 3) & 1))*16;
                LDSM4(b[2*j][0], b[2*j][1], b[2*j+1][0], b[2*j+1][1], addr);
            }
#pragma unroll
            for (int im = 0; im < 2; im++)
#pragma unroll
                for (int j = 0; j < NFR; j++)
                    MMA16816(acc[im][j], a[im], b[j]);
        }
    };

#pragma unroll
    for (int i = 0; i < STG-1; i++)
        if (i < ntiles) issue(i);

    for (int t = 0; t < ntiles; t++){
        int rem = ntiles - 1 - t;
        if (rem >= 2)      { CP_WAIT(2); }
        else if (rem == 1) { CP_WAIT(1); }
        else               { CP_WAIT(0); }
        __syncthreads();
        if (t + STG-1 < ntiles) issue(t + STG-1);
        compute(t);
    }

#pragma unroll
    for (int im = 0; im < 2; im++){
        int r = row0 + wm*32 + im*16 + (lane >> 2);
#pragma unroll
        for (int j = 0; j < NFR; j++){
            int c = col0 + wn*NW + j*8 + (lane & 3)*2;
            float v0 = acc[im][j][0], v1 = acc[im][j][1];
            float v2 = acc[im][j][2], v3 = acc[im][j][3];
            if (EPI == 1){
                float b0 = bias[c], b1 = bias[c+1];
                v0 += b0; v1 += b1; v2 += b0; v3 += b1;
                v0 = (v0 > 20.f) ? v0 : log1pf(fexp(v0));
                v1 = (v1 > 20.f) ? v1 : log1pf(fexp(v1));
                v2 = (v2 > 20.f) ? v2 : log1pf(fexp(v2));
                v3 = (v3 > 20.f) ? v3 : log1pf(fexp(v3));
            }
            *reinterpret_cast<float2*>(&Cp[(size_t)r*ldc + c])     = make_float2(v0, v1);
            *reinterpret_cast<float2*>(&Cp[(size_t)(r+8)*ldc + c]) = make_float2(v2, v3);
            if (EPI == 2){
                *reinterpret_cast<__half2*>(&C16[(size_t)r*ldc16 + c])     = __floats2half2_rn(v0, v1);
                *reinterpret_cast<__half2*>(&C16[(size_t)(r+8)*ldc16 + c]) = __floats2half2_rn(v2, v3);
            }
        }
    }
}

// ---------------- split-K reduce for xp gemm ----------------
__global__ void reduce_xp_kernel(){
    int idx = blockIdx.x*blockDim.x + threadIdx.x;
    if (idx >= MROWS*64) return;
    float s = g_part[idx] + g_part[MROWS*64 + idx]
            + g_part[2*MROWS*64 + idx] + g_part[3*MROWS*64 + idx];
    g_xdbl[idx] = s;
    int col = idx & 63;
    if (col < DTRANK){
        int row = idx >> 6;
        g_dtlr16[row*DTRANK + col] = __float2half(s);
    }
}

// ---------------- causal conv1d + silu (vectorized: 1 thread = 4 channels) ----------------
__global__ void conv_silu_kernel(const float* __restrict__ cw, const float* __restrict__ cb){
    int idx = blockIdx.x*blockDim.x + threadIdx.x;
    if (idx >= MROWS*(DINNER/4)) return;
    int r = idx >> 8;              // DINNER/4 = 256
    int e = (idx & 255) << 2;
    int b = r / LL, l = r % LL;

    float4 acc = *reinterpret_cast<const float4*>(cb + e);
    float cwv[4][4];
#pragma unroll
    for (int j = 0; j < 4; j++)
        *reinterpret_cast<float4*>(cwv[j]) =
            *reinterpret_cast<const float4*>(cw + (size_t)(e+j)*DCONV);

#pragma unroll
    for (int k = 0; k < DCONV; k++){
        int lp = l - (DCONV-1) + k;
        if (lp >= 0){
            float4 xc = *reinterpret_cast<const float4*>(
                g_xz + (size_t)(b*LL + lp)*(2*DINNER) + e);
            acc.x += cwv[0][k]*xc.x;
            acc.y += cwv[1][k]*xc.y;
            acc.z += cwv[2][k]*xc.z;
            acc.w += cwv[3][k]*xc.w;
        }
    }
    float4 u;
    u.x = fsilu(acc.x); u.y = fsilu(acc.y); u.z = fsilu(acc.z); u.w = fsilu(acc.w);
    size_t o = (size_t)r*DINNER + e;
    *reinterpret_cast<float4*>(g_u + o) = u;
    __half2 h01 = __floats2half2_rn(u.x, u.y);
    __half2 h23 = __floats2half2_rn(u.z, u.w);
    uint2 pk;
    pk.x = *reinterpret_cast<uint32_t*>(&h01);
    pk.y = *reinterpret_cast<uint32_t*>(&h23);
    *reinterpret_cast<uint2*>(g_u16 + o) = pk;

    float4 z = *reinterpret_cast<const float4*>(
        g_xz + (size_t)r*(2*DINNER) + DINNER + e);
    float4 sz;
    sz.x = fsilu(z.x); sz.y = fsilu(z.y); sz.z = fsilu(z.z); sz.w = fsilu(z.w);
    *reinterpret_cast<float4*>(g_sz + o) = sz;
}

// ---------------- selective scan v2: smem-staged, cp.async double buffered ----------------
// grid (DINNER/32, BB) = 128 blocks, 128 threads. 32-step chunks.
__global__ __launch_bounds__(128)
void scan_kernel(const float* __restrict__ A_log, const float* __restrict__ Dp){
    const int b = blockIdx.y;
    const int d0 = blockIdx.x*32;
    const int tid = threadIdx.x;
    const int w = tid >> 5, lane = tid & 31;
    const int col = w*8 + (lane & 7);
    const int d = d0 + col;
    const int sq = lane >> 3;

    __shared__ __align__(16) float s_dt[2][32][32];
    __shared__ __align__(16) float s_u [2][32][32];
    __shared__ __align__(16) float s_sz[2][32][32];
    __shared__ __align__(16) float s_bc[2][32][32];

    float a2[4];
#pragma unroll
    for (int k = 0; k < 4; k++)
        a2[k] = -expf(A_log[d*DSTATE + sq*4 + k]) * 1.4426950408889634f;
    const float dp = Dp[d];
    float st[4] = {0.f, 0.f, 0.f, 0.f};

    auto stage = [&](int c, int buf){
        int t0 = c*32;
#pragma unroll
        for (int kk = 0; kk < 2; kk++){
            int i = tid + kk*128;
            int tt = i >> 3, p = (i & 7) << 2;
            size_t g = ((size_t)(b*LL + t0 + tt))*DINNER + d0 + p;
            CP_ASYNC16(smem_u32(&s_dt[buf][tt][p]), g_dt + g);
            CP_ASYNC16(smem_u32(&s_u [buf][tt][p]), g_u  + g);
            CP_ASYNC16(smem_u32(&s_sz[buf][tt][p]), g_sz + g);
            size_t gb = ((size_t)(b*LL + t0 + tt))*64 + DTRANK + p;
            CP_ASYNC16(smem_u32(&s_bc[buf][tt][p]), g_xdbl + gb);
        }
        CP_COMMIT();
    };

    constexpr int NCH = LL/32;
    stage(0, 0);
    for (int c = 0; c < NCH; c++){
        const int buf = c & 1;
        if (c + 1 < NCH){ stage(c+1, buf^1); CP_WAIT(1); }
        else            { CP_WAIT(0); }
        __syncthreads();
#pragma unroll 8
        for (int tt = 0; tt < 32; tt++){
            float dt = s_dt[buf][tt][col];
            float uu = s_u [buf][tt][col];
            float du = dt*uu;
            float4 Bv = *reinterpret_cast<float4*>(&s_bc[buf][tt][sq*4]);
            float4 Cv = *reinterpret_cast<float4*>(&s_bc[buf][tt][16 + sq*4]);
            float dA0 = fx2(dt*a2[0]);
            float dA1 = fx2(dt*a2[1]);
            float dA2 = fx2(dt*a2[2]);
            float dA3 = fx2(dt*a2[3]);
            st[0] = dA0*st[0] + Bv.x*du;
            st[1] = dA1*st[1] + Bv.y*du;
            st[2] = dA2*st[2] + Bv.z*du;
            st[3] = dA3*st[3] + Bv.w*du;
            float y = st[0]*Cv.x + st[1]*Cv.y + st[2]*Cv.z + st[3]*Cv.w;
            y += __shfl_xor_sync(0xffffffffu, y, 8);
            y += __shfl_xor_sync(0xffffffffu, y, 16);
            if (sq == 0){
                size_t idx = ((size_t)(b*LL + c*32 + tt))*DINNER + d;
                g_y16[idx] = __float2half((y + uu*dp) * s_sz[buf][tt][col]);
            }
        }
        __syncthreads();
    }
}

// ---------------- final layernorm ----------------
__global__ __launch_bounds__(128)
void ln_kernel(const float* __restrict__ gamma, const float* __restrict__ beta,
               float* __restrict__ out){
    const int m = blockIdx.x;
    const int tid = threadIdx.x;
    const float4 v = reinterpret_cast<const float4*>(g_h + (size_t)m*DMODEL)[tid];
    float s  = v.x + v.y + v.z + v.w;
    float sq = v.x*v.x + v.y*v.y + v.z*v.z + v.w*v.w;
#pragma unroll
    for (int off = 16; off; off >>= 1){
        s  += __shfl_xor_sync(0xffffffffu, s,  off);
        sq += __shfl_xor_sync(0xffffffffu, sq, off);
    }
    __shared__ float r1[4], r2[4];
    if ((tid & 31) == 0){ r1[tid>>5] = s; r2[tid>>5] = sq; }
    __syncthreads();
    s  = r1[0] + r1[1] + r1[2] + r1[3];
    sq = r2[0] + r2[1] + r2[2] + r2[3];
    float mu  = s * (1.f/DMODEL);
    float var = sq * (1.f/DMODEL) - mu*mu;
    float rs  = rsqrtf(var + 1e-5f);
    float4 g4 = reinterpret_cast<const float4*>(gamma)[tid];
    float4 b4 = reinterpret_cast<const float4*>(beta)[tid];
    float4 o;
    o.x = (v.x - mu)*rs*g4.x + b4.x;
    o.y = (v.y - mu)*rs*g4.y + b4.y;
    o.z = (v.z - mu)*rs*g4.z + b4.z;
    o.w = (v.w - mu)*rs*g4.w + b4.w;
    reinterpret_cast<float4*>(out + (size_t)m*DMODEL)[tid] = o;
}

// ---------------- launch ----------------
extern "C" void kernel_launch(void* const* d_in, const int* in_sizes, int n_in,
                              void* d_out, int out_size){
    const float* x       = (const float*)d_in[0];
    const float* in_w    = (const float*)d_in[1];
    const float* in_b    = (const float*)d_in[2];
    const float* W_xz    = (const float*)d_in[3];
    const float* conv_w  = (const float*)d_in[4];
    const float* conv_b  = (const float*)d_in[5];
    const float* W_xp    = (const float*)d_in[6];
    const float* W_dt    = (const float*)d_in[7];
    const float* b_dt    = (const float*)d_in[8];
    const float* A_log   = (const float*)d_in[9];
    const float* D_param = (const float*)d_in[10];
    const float* W_out   = (const float*)d_in[11];
    const float* ln_g    = (const float*)d_in[12];
    const float* ln_b    = (const float*)d_in[13];
    float* out = (float*)d_out;

    float *ph, *pxz, *pdt, *ppart;
    __half *ph16, *pu16, *py16, *pdtlr16, *pw16;
    cudaGetSymbolAddress((void**)&ph,     g_h);
    cudaGetSymbolAddress((void**)&pxz,    g_xz);
    cudaGetSymbolAddress((void**)&pdt,    g_dt);
    cudaGetSymbolAddress((void**)&ppart,  g_part);
    cudaGetSymbolAddress((void**)&ph16,   g_h16);
    cudaGetSymbolAddress((void**)&pu16,   g_u16);
    cudaGetSymbolAddress((void**)&py16,   g_y16);
    cudaGetSymbolAddress((void**)&pdtlr16,g_dtlr16);
    cudaGetSymbolAddress((void**)&pw16,   g_w16);

    const int SM128 = 4*(128*80 + 128*80);   // 81920
    const int SM64  = 4*(128*80 + 64*80);    // 61440
    cudaFuncSetAttribute(gemm_h<128,0>, cudaFuncAttributeMaxDynamicSharedMemorySize, SM128);
    cudaFuncSetAttribute(gemm_h<128,1>, cudaFuncAttributeMaxDynamicSharedMemorySize, SM128);
    cudaFuncSetAttribute(gemm_h<128,2>, cudaFuncAttributeMaxDynamicSharedMemorySize, SM128);
    cudaFuncSetAttribute(gemm_h<64,0>,  cudaFuncAttributeMaxDynamicSharedMemorySize, SM64);

    // Launch order: slot 4 (ncu capture) = layer-0 conv_silu
    inproj_kernel<<<(MROWS*DMODEL)/128, 128>>>(x, in_w, in_b);                                   // 1
    f2h_kernel<<<(NDEPTH*SZ_XZ_L/4 + 255)/256, 256>>>(W_xz,  pw16 + OFF_XZ,  NDEPTH*SZ_XZ_L/4); // 2

    // 3 — xz GEMM layer 0
    gemm_h<128,0><<<dim3(2048/128, MROWS/128, 1), 256, SM128>>>(
        ph16, pw16 + OFF_XZ, pxz,
        DMODEL, DMODEL, DMODEL, 2*DINNER, nullptr, nullptr, 0, 0);

    // 4 — PROFILED: conv layer 0
    conv_silu_kernel<<<(MROWS*(DINNER/4))/256, 256>>>(conv_w, conv_b);

    f2h_kernel<<<(NDEPTH*SZ_XP_L/4 + 255)/256, 256>>>(W_xp,  pw16 + OFF_XP,  NDEPTH*SZ_XP_L/4); // 5
    f2h_kernel<<<(NDEPTH*SZ_DT_L/4 + 255)/256, 256>>>(W_dt,  pw16 + OFF_DT,  NDEPTH*SZ_DT_L/4); // 6
    f2h_kernel<<<(NDEPTH*SZ_OUT_L/4 + 255)/256, 256>>>(W_out, pw16 + OFF_OUT, NDEPTH*SZ_OUT_L/4);//7

    for (int lyr = 0; lyr < NDEPTH; lyr++){
        if (lyr > 0){
            gemm_h<128,0><<<dim3(2048/128, MROWS/128, 1), 256, SM128>>>(
                ph16, pw16 + OFF_XZ + (size_t)lyr*SZ_XZ_L, pxz,
                DMODEL, DMODEL, DMODEL, 2*DINNER, nullptr, nullptr, 0, 0);
            conv_silu_kernel<<<(MROWS*(DINNER/4))/256, 256>>>(
                conv_w + (size_t)lyr*DINNER*DCONV, conv_b + (size_t)lyr*DINNER);
        }

        // xdbl = u @ Wxp^T    M=4096 N=64 K=1024, split-K=4
        gemm_h<64,0><<<dim3(1, MROWS/128, 4), 256, SM64>>>(
            pu16, pw16 + OFF_XP + (size_t)lyr*SZ_XP_L, ppart,
            DINNER, DINNER, DINNER, 64, nullptr, nullptr, 0, MROWS*64);

        reduce_xp_kernel<<<(MROWS*64)/256, 256>>>();

        // dt = softplus(dt_lr @ Wdt^T + b_dt)   M=4096 N=1024 K=32
        gemm_h<128,1><<<dim3(DINNER/128, MROWS/128, 1), 256, SM128>>>(
            pdtlr16, pw16 + OFF_DT + (size_t)lyr*SZ_DT_L, pdt,
            DTRANK, DTRANK, DTRANK, DINNER, b_dt + (size_t)lyr*DINNER, nullptr, 0, 0);

        scan_kernel<<<dim3(DINNER/32, BB), 128>>>(
            A_log + (size_t)lyr*DINNER*DSTATE, D_param + (size_t)lyr*DINNER);

        // h = y @ Wout^T      M=4096 N=512 K=1024  (dual write fp32 + fp16)
        gemm_h<128,2><<<dim3(DMODEL/128, MROWS/128, 1), 256, SM128>>>(
            py16, pw16 + OFF_OUT + (size_t)lyr*SZ_OUT_L, ph,
            DINNER, DINNER, DINNER, DMODEL, nullptr, ph16, DMODEL, 0);
    }

    ln_kernel<<<MROWS, 128>>>(ln_g, ln_b, out);
}